// round 1
// baseline (speedup 1.0000x reference)
#include <cuda_runtime.h>
#include <math.h>
#include <stdint.h>

// Problem constants
#define Bn 16
#define Nn 1024
#define Dn 256
#define Hn 128
#define Sn 12     // MAX_CLUSTERS
#define CSn 16    // CSIZE
#define NEGV (-1e9f)

// JAX threefry_partitionable default (jax >= 0.5). Set to 0 for legacy path.
#define PARTITIONABLE 1

// ---------------- scratch (no allocations allowed) ----------------
__device__ float g_XW1t[Bn * Hn * Nn];      // [b][h][n] = x@W1[:256] + b1
__device__ float g_WihT[Dn * 3 * Hn];       // [256][384]
__device__ float g_WhhT[Hn * 3 * Hn];       // [128][384]

// ---------------- Threefry2x32 (JAX-exact) ----------------
__device__ __forceinline__ uint2 tf2x32(unsigned k0, unsigned k1, unsigned x0, unsigned x1) {
    unsigned ks2 = k0 ^ k1 ^ 0x1BD11BDAu;
    x0 += k0; x1 += k1;
#define TFR(r) { x0 += x1; x1 = (x1 << (r)) | (x1 >> (32 - (r))); x1 ^= x0; }
    TFR(13) TFR(15) TFR(26) TFR(6)   x0 += k1;  x1 += ks2 + 1u;
    TFR(17) TFR(29) TFR(16) TFR(24)  x0 += ks2; x1 += k0 + 2u;
    TFR(13) TFR(15) TFR(26) TFR(6)   x0 += k0;  x1 += k1 + 3u;
    TFR(17) TFR(29) TFR(16) TFR(24)  x0 += k1;  x1 += ks2 + 4u;
    TFR(13) TFR(15) TFR(26) TFR(6)   x0 += ks2; x1 += k0 + 5u;
#undef TFR
    return make_uint2(x0, x1);
}

// compile-time version for the key chain
struct P2 { unsigned x, y; };
constexpr unsigned rotl_c(unsigned x, int r) { return (x << r) | (x >> (32 - r)); }
constexpr P2 tf_c(unsigned k0, unsigned k1, unsigned x0, unsigned x1) {
    unsigned ks2 = k0 ^ k1 ^ 0x1BD11BDAu;
    x0 += k0; x1 += k1;
    const int R0[4] = {13, 15, 26, 6};
    const int R1[4] = {17, 29, 16, 24};
    for (int i = 0; i < 5; i++) {
        for (int j = 0; j < 4; j++) {
            int r = (i % 2 == 0) ? R0[j] : R1[j];
            x0 += x1; x1 = rotl_c(x1, r); x1 ^= x0;
        }
        int a = (i + 1) % 3, bsel = (i + 2) % 3;
        unsigned inj0 = (a == 0) ? k0 : ((a == 1) ? k1 : ks2);
        unsigned inj1 = (bsel == 0) ? k0 : ((bsel == 1) ? k1 : ks2);
        x0 += inj0; x1 += inj1 + (unsigned)(i + 1);
    }
    return P2{x0, x1};
}

struct KeyTab { unsigned a[Sn * CSn]; unsigned b[Sn * CSn]; };
constexpr KeyTab mk_keys() {
    KeyTab t{};
    unsigned k0 = 0u, k1 = 42u;  // jax.random.key(42)
    for (int i = 0; i < Sn * CSn; i++) {
#if PARTITIONABLE
        P2 nk = tf_c(k0, k1, 0u, 0u);   // keys[0] -> next master
        P2 sk = tf_c(k0, k1, 0u, 1u);   // keys[1] -> selection key
        t.a[i] = sk.x; t.b[i] = sk.y;
        k0 = nk.x; k1 = nk.y;
#else
        P2 l0 = tf_c(k0, k1, 0u, 2u);
        P2 l1 = tf_c(k0, k1, 1u, 3u);
        t.a[i] = l0.y; t.b[i] = l1.y;   // ks = (out1 of lane0, out1 of lane1)
        k0 = l0.x; k1 = l1.x;           // key = (out0 of lane0, out0 of lane1)
#endif
    }
    return t;
}
static constexpr KeyTab H_KEYS = mk_keys();
__constant__ KeyTab SELKEYS = H_KEYS;

// uniform bits for flat index g under key (k0,k1)
__device__ __forceinline__ unsigned rand_bits(unsigned k0, unsigned k1, unsigned g) {
#if PARTITIONABLE
    uint2 o = tf2x32(k0, k1, 0u, g);
    return o.x ^ o.y;
#else
    const unsigned m = (Bn * Nn) / 2;   // 8192
    if (g < m) { uint2 o = tf2x32(k0, k1, g, g + m); return o.x; }
    else       { uint2 o = tf2x32(k0, k1, g - m, g); return o.y; }
#endif
}

__device__ __forceinline__ float sigm(float v) {
    // XLA logistic lowering: 0.5 + 0.5*tanh(0.5*x)
    return 0.5f * tanhf(0.5f * v) + 0.5f;
}

// ---------------- Kernel 1: XW1t[b][j][n] = x[b,n,:256] @ W1[:256,j] + b1[j] ----------------
__global__ void k_xw1(const float* __restrict__ x, const float* __restrict__ W1,
                      const float* __restrict__ b1) {
    int tile = blockIdx.x;       // 0..31  (32 n per tile)
    int b = blockIdx.y;
    int t = threadIdx.x;         // 256
    __shared__ float xs[32 * 257];
    int n0 = tile * 32;
    for (int i = t; i < 32 * 256; i += 256) {
        int n = i >> 8, k = i & 255;
        xs[n * 257 + k] = x[((b << 10) + (n0 + n)) * Dn + k];
    }
    __syncthreads();
    int n = t & 31;
    int jg = t >> 5;             // 0..7
    float acc[16];
#pragma unroll
    for (int i = 0; i < 16; i++) acc[i] = 0.f;
    for (int k = 0; k < 256; k++) {
        float xv = xs[n * 257 + k];
        const float* wrow = W1 + k * Hn + jg;
#pragma unroll
        for (int i = 0; i < 16; i++) acc[i] = fmaf(xv, wrow[8 * i], acc[i]);
    }
#pragma unroll
    for (int i = 0; i < 16; i++) {
        int j = jg + 8 * i;
        g_XW1t[((b << 7) + j) * Nn + n0 + n] = acc[i] + b1[j];
    }
}

// ---------------- Kernel 2: transpose GRU weights ----------------
__global__ void k_transpose(const float* __restrict__ Wih, const float* __restrict__ Whh) {
    int idx = blockIdx.x * blockDim.x + threadIdx.x;
    if (idx < 384 * 256) { int j = idx / 256, k = idx % 256; g_WihT[k * 384 + j] = Wih[idx]; }
    if (idx < 384 * 128) { int j = idx / 128, k = idx % 128; g_WhhT[k * 384 + j] = Whh[idx]; }
}

// ---------------- Main kernel: one block per batch ----------------
__global__ void __launch_bounds__(1024) k_main(
    const float* __restrict__ x, const float* __restrict__ adj,
    const float* __restrict__ W1, const float* __restrict__ W2, const float* __restrict__ b2,
    const float* __restrict__ bih, const float* __restrict__ bhh,
    const float* __restrict__ Wc, const float* __restrict__ bc,
    float* __restrict__ out) {
    int b = blockIdx.x;
    int n = threadIdx.x;
    int lane = n & 31, wid = n >> 5;

    __shared__ float s_logit[Nn];
    __shared__ float s_ctx[Hn], s_gctx[Hn], s_hidden[Hn];
    __shared__ float s_gh[3 * Hn];
    __shared__ float s_gi[Sn][3 * Hn];
    __shared__ float s_emb[Dn];
    __shared__ float s_w2[Hn];
    __shared__ float s_xmean[Dn];
    __shared__ unsigned char s_avail[Nn], s_mem[Nn], s_kmask[Nn], s_reach[Nn], s_cur[Nn];
    __shared__ int s_flist[Nn];
    __shared__ int s_fcnt;
    __shared__ unsigned long long s_red[32];
    __shared__ int s_sel, s_valid;
    __shared__ int s_mlist[CSn];
    __shared__ int s_mcnt;

    s_avail[n] = 1;  // mask is all-ones by construction
    if (n < Dn) {
        float s = 0.f;
        for (int m = 0; m < Nn; m++) s += x[((b << 10) + m) * Dn + n];
        s_xmean[n] = s / 1024.0f;
    }
    if (n < Hn) s_w2[n] = W2[n];
    __syncthreads();
    if (n < Hn) {
        float a = bc[n];
        for (int d = 0; d < Dn; d++) a = fmaf(s_xmean[d], Wc[d * Hn + n], a);
        s_gctx[n] = a;
        s_hidden[n] = 0.f;
    }
    float b2v = b2[0];
    __syncthreads();

    float* out_cf = out;                       // [16][12][256]
    float* out_ca = out + Bn * Sn * Dn;        // [16][12][12]
    float* out_as = out_ca + Bn * Sn * Sn;     // [16][1024][12]

    for (int c = 0; c < Sn; c++) {
        s_mem[n] = 0;
        __syncthreads();
        // ctx contribution: gctx @ W1[256:384,:]
        if (n < Hn) {
            float a = 0.f;
            for (int k = 0; k < Hn; k++) a = fmaf(s_gctx[k], W1[(Dn + k) * Hn + n], a);
            s_ctx[n] = a;
        }
        __syncthreads();
        // logits[n] = relu(XW1t + ctx) @ W2 + b2
        {
            float acc = 0.f;
            const float* px = g_XW1t + ((long)(b) << 7) * Nn + n;
#pragma unroll 8
            for (int j = 0; j < Hn; j++) {
                float v = px[j * Nn] + s_ctx[j];
                acc = fmaf(fmaxf(v, 0.f), s_w2[j], acc);
            }
            s_logit[n] = acc + b2v;
        }
        __syncthreads();

        // ---- 16 sequential selections ----
        for (int s = 0; s < CSn; s++) {
            bool cand = s_avail[n] && (s == 0 || s_kmask[n]);
            float val = NEGV;
            if (cand) {
                unsigned k0 = SELKEYS.a[c * CSn + s], k1 = SELKEYS.b[c * CSn + s];
                unsigned bits = rand_bits(k0, k1, (unsigned)((b << 10) + n));
                float u = __uint_as_float((bits >> 9) | 0x3f800000u) - 1.0f;
                float s1 = u + 1e-8f;
                float l1 = (float)log((double)s1);
                float s2 = (-l1) + 1e-8f;
                float l2 = (float)log((double)s2);
                val = s_logit[n] + (-l2);      // TAU = 1
            }
            unsigned ub = __float_as_uint(val);
            unsigned ord = (ub & 0x80000000u) ? ~ub : (ub | 0x80000000u);
            unsigned long long pk =
                (((unsigned long long)ord) << 32) | (unsigned)(0xFFFFFFFFu - n);
            for (int off = 16; off; off >>= 1) {
                unsigned long long o = __shfl_down_sync(0xffffffffu, pk, off);
                if (o > pk) pk = o;
            }
            if (lane == 0) s_red[wid] = pk;
            __syncthreads();
            if (wid == 0) {
                unsigned long long v2 = s_red[lane];
                for (int off = 16; off; off >>= 1) {
                    unsigned long long o = __shfl_down_sync(0xffffffffu, v2, off);
                    if (o > v2) v2 = o;
                }
                if (lane == 0) {
                    s_sel = (int)(0xFFFFFFFFu - (unsigned)(v2 & 0xFFFFFFFFu));
                    unsigned ordv = (unsigned)(v2 >> 32);
                    unsigned fb = (ordv & 0x80000000u) ? (ordv ^ 0x80000000u) : ~ordv;
                    s_valid = (__uint_as_float(fb) > -1e8f) ? 1 : 0;
                }
            }
            __syncthreads();
            int sel = s_sel;
            if (s_valid && n == sel) { s_avail[n] = 0; s_mem[n] = 1; }

            if (s == 0) {
                // 2-hop BFS from seed (index used even if invalid, matching JAX)
                s_reach[n] = (n == sel);
                s_cur[n] = (n == sel);
                __syncthreads();
                for (int hop = 0; hop < 2; hop++) {
                    if (n == 0) s_fcnt = 0;
                    __syncthreads();
                    if (s_cur[n]) { int p = atomicAdd(&s_fcnt, 1); s_flist[p] = n; }
                    __syncthreads();
                    int fc = s_fcnt;
                    bool nb = false;
                    const float* arow = adj + ((long)b << 20);
                    for (int f = 0; f < fc; f++)
                        nb = nb || (arow[(s_flist[f] << 10) + n] != 0.0f);
                    bool old = s_reach[n];
                    __syncthreads();
                    s_cur[n] = nb && !old;
                    s_reach[n] = old || nb;
                    __syncthreads();
                }
                s_kmask[n] = s_reach[n];
                __syncthreads();
            }
        }
        __syncthreads();

        // ---- cluster embedding (deterministic ascending-index sum) ----
        if (n == 0) {
            int mc = 0;
            for (int m = 0; m < Nn; m++)
                if (s_mem[m]) s_mlist[mc++] = m;
            s_mcnt = mc;
        }
        __syncthreads();
        int mc = s_mcnt;
        if (n < Dn) {
            float e = 0.f;
            for (int i = 0; i < mc; i++) e += x[((b << 10) + s_mlist[i]) * Dn + n];
            e = e / fmaxf((float)mc, 1.0f);
            s_emb[n] = e;
            out_cf[((b * Sn) + c) * Dn + n] = e;
        }
        out_as[((b << 10) + n) * Sn + c] = s_mem[n] ? 1.0f : 0.0f;
        __syncthreads();

        // cache gi for this cluster's emb (input-side GRU gates)
        if (n < 3 * Hn) {
            float a = bih[n];
            for (int k = 0; k < Dn; k++) a = fmaf(s_emb[k], g_WihT[k * 384 + n], a);
            s_gi[c][n] = a;
        }
        __syncthreads();

        // GRU re-scan over embs[0..c] from current hidden
        for (int t2 = 0; t2 <= c; t2++) {
            if (n < 3 * Hn) {
                float a = bhh[n];
                for (int k = 0; k < Hn; k++) a = fmaf(s_hidden[k], g_WhhT[k * 384 + n], a);
                s_gh[n] = a;
            }
            __syncthreads();
            if (n < Hn) {
                float ir = s_gi[t2][n], iz = s_gi[t2][Hn + n], inn = s_gi[t2][2 * Hn + n];
                float hr = s_gh[n], hz = s_gh[Hn + n], hn = s_gh[2 * Hn + n];
                float r = sigm(ir + hr);
                float z = sigm(iz + hz);
                float nn = tanhf(inn + r * hn);
                float hprev = s_hidden[n];
                s_hidden[n] = (1.0f - z) * nn + z * hprev;
            }
            __syncthreads();
        }
        if (n < Hn) s_gctx[n] = s_hidden[n];
        __syncthreads();
    }

    // cluster_adj = ones - eye
    if (n < Sn * Sn) {
        int i = n / Sn, j = n % Sn;
        out_ca[b * Sn * Sn + n] = (i == j) ? 0.0f : 1.0f;
    }
}

extern "C" void kernel_launch(void* const* d_in, const int* in_sizes, int n_in,
                              void* d_out, int out_size) {
    (void)in_sizes; (void)out_size;
    // inputs: x, adj, mask, W1, b1, W2, b2, Wih, Whh, bih, bhh, Wc, bc
    int k = (n_in >= 13) ? 3 : 2;   // tolerate mask being dropped
    const float* x   = (const float*)d_in[0];
    const float* adj = (const float*)d_in[1];
    const float* W1  = (const float*)d_in[k + 0];
    const float* b1  = (const float*)d_in[k + 1];
    const float* W2  = (const float*)d_in[k + 2];
    const float* b2  = (const float*)d_in[k + 3];
    const float* Wih = (const float*)d_in[k + 4];
    const float* Whh = (const float*)d_in[k + 5];
    const float* bih = (const float*)d_in[k + 6];
    const float* bhh = (const float*)d_in[k + 7];
    const float* Wc  = (const float*)d_in[k + 8];
    const float* bc  = (const float*)d_in[k + 9];

    k_xw1<<<dim3(32, Bn), 256>>>(x, W1, b1);
    k_transpose<<<(384 * 256 + 255) / 256, 256>>>(Wih, Whh);
    k_main<<<Bn, 1024>>>(x, adj, W1, W2, b2, bih, bhh, Wc, bc, (float*)d_out);
}

// round 3
// speedup vs baseline: 1.1662x; 1.1662x over previous
#include <cuda_runtime.h>
#include <math.h>
#include <stdint.h>

// Problem constants
#define Bn 16
#define Nn 1024
#define Dn 256
#define Hn 128
#define Sn 12     // MAX_CLUSTERS
#define CSn 16    // CSIZE
#define NEGV (-1e9f)

// JAX threefry_partitionable default (jax >= 0.5). Set to 0 for legacy path.
#define PARTITIONABLE 1

// ---------------- scratch (no allocations allowed) ----------------
__device__ float g_XW1t[Bn * Hn * Nn];      // [b][h][n] = x@W1[:256] + b1
__device__ float g_WihT[Dn * 3 * Hn];       // [256][384]
__device__ float g_WhhT[Hn * 3 * Hn];       // [128][384]

// ---------------- Threefry2x32 (JAX-exact) ----------------
__device__ __forceinline__ uint2 tf2x32(unsigned k0, unsigned k1, unsigned x0, unsigned x1) {
    unsigned ks2 = k0 ^ k1 ^ 0x1BD11BDAu;
    x0 += k0; x1 += k1;
#define TFR(r) { x0 += x1; x1 = (x1 << (r)) | (x1 >> (32 - (r))); x1 ^= x0; }
    TFR(13) TFR(15) TFR(26) TFR(6)   x0 += k1;  x1 += ks2 + 1u;
    TFR(17) TFR(29) TFR(16) TFR(24)  x0 += ks2; x1 += k0 + 2u;
    TFR(13) TFR(15) TFR(26) TFR(6)   x0 += k0;  x1 += k1 + 3u;
    TFR(17) TFR(29) TFR(16) TFR(24)  x0 += k1;  x1 += ks2 + 4u;
    TFR(13) TFR(15) TFR(26) TFR(6)   x0 += ks2; x1 += k0 + 5u;
#undef TFR
    return make_uint2(x0, x1);
}

// compile-time version for the key chain
struct P2 { unsigned x, y; };
constexpr unsigned rotl_c(unsigned x, int r) { return (x << r) | (x >> (32 - r)); }
constexpr P2 tf_c(unsigned k0, unsigned k1, unsigned x0, unsigned x1) {
    unsigned ks2 = k0 ^ k1 ^ 0x1BD11BDAu;
    x0 += k0; x1 += k1;
    const int R0[4] = {13, 15, 26, 6};
    const int R1[4] = {17, 29, 16, 24};
    for (int i = 0; i < 5; i++) {
        for (int j = 0; j < 4; j++) {
            int r = (i % 2 == 0) ? R0[j] : R1[j];
            x0 += x1; x1 = rotl_c(x1, r); x1 ^= x0;
        }
        int a = (i + 1) % 3, bsel = (i + 2) % 3;
        unsigned inj0 = (a == 0) ? k0 : ((a == 1) ? k1 : ks2);
        unsigned inj1 = (bsel == 0) ? k0 : ((bsel == 1) ? k1 : ks2);
        x0 += inj0; x1 += inj1 + (unsigned)(i + 1);
    }
    return P2{x0, x1};
}

struct KeyTab { unsigned a[Sn * CSn]; unsigned b[Sn * CSn]; };
constexpr KeyTab mk_keys() {
    KeyTab t{};
    unsigned k0 = 0u, k1 = 42u;  // jax.random.key(42)
    for (int i = 0; i < Sn * CSn; i++) {
#if PARTITIONABLE
        P2 nk = tf_c(k0, k1, 0u, 0u);   // keys[0] -> next master
        P2 sk = tf_c(k0, k1, 0u, 1u);   // keys[1] -> selection key
        t.a[i] = sk.x; t.b[i] = sk.y;
        k0 = nk.x; k1 = nk.y;
#else
        P2 l0 = tf_c(k0, k1, 0u, 2u);
        P2 l1 = tf_c(k0, k1, 1u, 3u);
        t.a[i] = l0.y; t.b[i] = l1.y;   // ks = (out1 of lane0, out1 of lane1)
        k0 = l0.x; k1 = l1.x;           // key = (out0 of lane0, out0 of lane1)
#endif
    }
    return t;
}
static constexpr KeyTab H_KEYS = mk_keys();
__constant__ KeyTab SELKEYS = H_KEYS;

// uniform bits for flat index g under key (k0,k1)
__device__ __forceinline__ unsigned rand_bits(unsigned k0, unsigned k1, unsigned g) {
#if PARTITIONABLE
    uint2 o = tf2x32(k0, k1, 0u, g);
    return o.x ^ o.y;
#else
    const unsigned m = (Bn * Nn) / 2;   // 8192
    if (g < m) { uint2 o = tf2x32(k0, k1, g, g + m); return o.x; }
    else       { uint2 o = tf2x32(k0, k1, g - m, g); return o.y; }
#endif
}

__device__ __forceinline__ float sigm(float v) {
    // XLA logistic lowering: 0.5 + 0.5*tanh(0.5*x)
    return 0.5f * tanhf(0.5f * v) + 0.5f;
}

// ---------------- Kernel 1 (v3, smem-tiled SGEMM, k-chunk 32 to fit 48KB):
// XW1t[b][j][n] = x[b,n,:256] @ W1[:256,j] + b1[j]
// 64n x 128j tile per block. Accumulation over k strictly ascending =>
// bitwise-identical to the original per-n loop.
__global__ void __launch_bounds__(256) k_xw1(const float* __restrict__ x,
                                             const float* __restrict__ W1,
                                             const float* __restrict__ b1) {
    __shared__ float xs[64][33];    // [n][k] padded -> conflict-free
    __shared__ float ws[32][128];   // [k][j], reads are warp-broadcast
    int tile = blockIdx.x;          // 0..15 (64 n per tile)
    int b = blockIdx.y;
    int t = threadIdx.x;            // 256
    int n0 = tile * 64;
    int nl = t & 63;
    int jbase = (t >> 6) * 32;      // 0,32,64,96

    float acc[32];
#pragma unroll
    for (int i = 0; i < 32; i++) acc[i] = 0.f;

    for (int k0 = 0; k0 < Dn; k0 += 32) {
        for (int i = t; i < 64 * 32; i += 256) {
            int nn = i >> 5, kk = i & 31;
            xs[nn][kk] = x[((b << 10) + n0 + nn) * Dn + k0 + kk];
        }
        for (int i = t; i < 32 * 128; i += 256) {
            int kk = i >> 7, jj = i & 127;
            ws[kk][jj] = W1[(k0 + kk) * Hn + jj];
        }
        __syncthreads();
#pragma unroll 4
        for (int k = 0; k < 32; k++) {
            float xv = xs[nl][k];
            const float4* w4 = reinterpret_cast<const float4*>(&ws[k][jbase]);
#pragma unroll
            for (int i = 0; i < 8; i++) {
                float4 w = w4[i];
                acc[4 * i + 0] = fmaf(xv, w.x, acc[4 * i + 0]);
                acc[4 * i + 1] = fmaf(xv, w.y, acc[4 * i + 1]);
                acc[4 * i + 2] = fmaf(xv, w.z, acc[4 * i + 2]);
                acc[4 * i + 3] = fmaf(xv, w.w, acc[4 * i + 3]);
            }
        }
        __syncthreads();
    }
#pragma unroll
    for (int i = 0; i < 32; i++) {
        int j = jbase + i;
        g_XW1t[((b << 7) + j) * Nn + n0 + nl] = acc[i] + b1[j];
    }
}

// ---------------- Kernel 2: transpose GRU weights ----------------
__global__ void k_transpose(const float* __restrict__ Wih, const float* __restrict__ Whh) {
    int idx = blockIdx.x * blockDim.x + threadIdx.x;
    if (idx < 384 * 256) { int j = idx / 256, k = idx % 256; g_WihT[k * 384 + j] = Wih[idx]; }
    if (idx < 384 * 128) { int j = idx / 128, k = idx % 128; g_WhhT[k * 384 + j] = Whh[idx]; }
}

// ---------------- Main kernel: one block per batch ----------------
__global__ void __launch_bounds__(1024) k_main(
    const float* __restrict__ x, const float* __restrict__ adj,
    const float* __restrict__ W1, const float* __restrict__ W2, const float* __restrict__ b2,
    const float* __restrict__ bih, const float* __restrict__ bhh,
    const float* __restrict__ Wc, const float* __restrict__ bc,
    float* __restrict__ out) {
    int b = blockIdx.x;
    int n = threadIdx.x;
    int lane = n & 31, wid = n >> 5;

    __shared__ float s_logit[Nn];
    __shared__ float s_ctx[Hn], s_gctx[Hn], s_hidden[Hn];
    __shared__ float s_gh[3 * Hn];
    __shared__ float s_gi[Sn][3 * Hn];
    __shared__ float s_emb[Dn];
    __shared__ float s_w2[Hn];
    __shared__ float s_xmean[Dn];
    __shared__ unsigned char s_avail[Nn], s_mem[Nn], s_kmask[Nn], s_reach[Nn], s_cur[Nn];
    __shared__ int s_flist[Nn];
    __shared__ int s_fcnt;
    __shared__ unsigned long long s_red[32];
    __shared__ int s_sel, s_valid;
    __shared__ int s_mlist[CSn];
    __shared__ int s_mcnt;

    s_avail[n] = 1;  // mask is all-ones by construction
    if (n < Dn) {
        float s = 0.f;
        for (int m = 0; m < Nn; m++) s += x[((b << 10) + m) * Dn + n];
        s_xmean[n] = s / 1024.0f;
    }
    if (n < Hn) s_w2[n] = W2[n];
    __syncthreads();
    if (n < Hn) {
        float a = bc[n];
        for (int d = 0; d < Dn; d++) a = fmaf(s_xmean[d], Wc[d * Hn + n], a);
        s_gctx[n] = a;
        s_hidden[n] = 0.f;
    }
    float b2v = b2[0];
    __syncthreads();

    float* out_cf = out;                       // [16][12][256]
    float* out_ca = out + Bn * Sn * Dn;        // [16][12][12]
    float* out_as = out_ca + Bn * Sn * Sn;     // [16][1024][12]

    for (int c = 0; c < Sn; c++) {
        s_mem[n] = 0;
        __syncthreads();
        // ctx contribution: gctx @ W1[256:384,:]
        if (n < Hn) {
            float a = 0.f;
            for (int k = 0; k < Hn; k++) a = fmaf(s_gctx[k], W1[(Dn + k) * Hn + n], a);
            s_ctx[n] = a;
        }
        __syncthreads();
        // logits[n] = relu(XW1t + ctx) @ W2 + b2
        {
            float acc = 0.f;
            const float* px = g_XW1t + ((long)(b) << 7) * Nn + n;
#pragma unroll 8
            for (int j = 0; j < Hn; j++) {
                float v = px[j * Nn] + s_ctx[j];
                acc = fmaf(fmaxf(v, 0.f), s_w2[j], acc);
            }
            s_logit[n] = acc + b2v;
        }
        __syncthreads();

        // ---- 16 sequential selections ----
        for (int s = 0; s < CSn; s++) {
            bool cand = s_avail[n] && (s == 0 || s_kmask[n]);
            float val = NEGV;
            if (cand) {
                unsigned k0 = SELKEYS.a[c * CSn + s], k1 = SELKEYS.b[c * CSn + s];
                unsigned bits = rand_bits(k0, k1, (unsigned)((b << 10) + n));
                float u = __uint_as_float((bits >> 9) | 0x3f800000u) - 1.0f;
                float s1 = u + 1e-8f;
                float l1 = logf(s1);
                float s2 = (-l1) + 1e-8f;
                float l2 = logf(s2);
                val = s_logit[n] + (-l2);      // TAU = 1
            }
            unsigned ub = __float_as_uint(val);
            unsigned ord = (ub & 0x80000000u) ? ~ub : (ub | 0x80000000u);
            unsigned long long pk =
                (((unsigned long long)ord) << 32) | (unsigned)(0xFFFFFFFFu - n);
            for (int off = 16; off; off >>= 1) {
                unsigned long long o = __shfl_down_sync(0xffffffffu, pk, off);
                if (o > pk) pk = o;
            }
            if (lane == 0) s_red[wid] = pk;
            __syncthreads();
            if (wid == 0) {
                unsigned long long v2 = s_red[lane];
                for (int off = 16; off; off >>= 1) {
                    unsigned long long o = __shfl_down_sync(0xffffffffu, v2, off);
                    if (o > v2) v2 = o;
                }
                if (lane == 0) {
                    s_sel = (int)(0xFFFFFFFFu - (unsigned)(v2 & 0xFFFFFFFFu));
                    unsigned ordv = (unsigned)(v2 >> 32);
                    unsigned fb = (ordv & 0x80000000u) ? (ordv ^ 0x80000000u) : ~ordv;
                    s_valid = (__uint_as_float(fb) > -1e8f) ? 1 : 0;
                }
            }
            __syncthreads();
            int sel = s_sel;
            if (s_valid && n == sel) { s_avail[n] = 0; s_mem[n] = 1; }

            if (s == 0) {
                // 2-hop BFS from seed (index used even if invalid, matching JAX)
                s_reach[n] = (n == sel);
                s_cur[n] = (n == sel);
                __syncthreads();
                for (int hop = 0; hop < 2; hop++) {
                    if (n == 0) s_fcnt = 0;
                    __syncthreads();
                    if (s_cur[n]) { int p = atomicAdd(&s_fcnt, 1); s_flist[p] = n; }
                    __syncthreads();
                    int fc = s_fcnt;
                    bool nb = false;
                    const float* arow = adj + ((long)b << 20);
                    for (int f = 0; f < fc; f++)
                        nb = nb || (arow[(s_flist[f] << 10) + n] != 0.0f);
                    bool old = s_reach[n];
                    __syncthreads();
                    s_cur[n] = nb && !old;
                    s_reach[n] = old || nb;
                    __syncthreads();
                }
                s_kmask[n] = s_reach[n];
                __syncthreads();
            }
        }
        __syncthreads();

        // ---- cluster embedding (deterministic ascending-index sum) ----
        if (n == 0) {
            int mc = 0;
            for (int m = 0; m < Nn; m++)
                if (s_mem[m]) s_mlist[mc++] = m;
            s_mcnt = mc;
        }
        __syncthreads();
        int mc = s_mcnt;
        if (n < Dn) {
            float e = 0.f;
            for (int i = 0; i < mc; i++) e += x[((b << 10) + s_mlist[i]) * Dn + n];
            e = e / fmaxf((float)mc, 1.0f);
            s_emb[n] = e;
            out_cf[((b * Sn) + c) * Dn + n] = e;
        }
        out_as[((b << 10) + n) * Sn + c] = s_mem[n] ? 1.0f : 0.0f;
        __syncthreads();

        // cache gi for this cluster's emb (input-side GRU gates)
        if (n < 3 * Hn) {
            float a = bih[n];
            for (int k = 0; k < Dn; k++) a = fmaf(s_emb[k], g_WihT[k * 384 + n], a);
            s_gi[c][n] = a;
        }
        __syncthreads();

        // GRU re-scan over embs[0..c] from current hidden
        for (int t2 = 0; t2 <= c; t2++) {
            if (n < 3 * Hn) {
                float a = bhh[n];
                for (int k = 0; k < Hn; k++) a = fmaf(s_hidden[k], g_WhhT[k * 384 + n], a);
                s_gh[n] = a;
            }
            __syncthreads();
            if (n < Hn) {
                float ir = s_gi[t2][n], iz = s_gi[t2][Hn + n], inn = s_gi[t2][2 * Hn + n];
                float hr = s_gh[n], hz = s_gh[Hn + n], hn = s_gh[2 * Hn + n];
                float r = sigm(ir + hr);
                float z = sigm(iz + hz);
                float nn = tanhf(inn + r * hn);
                float hprev = s_hidden[n];
                s_hidden[n] = (1.0f - z) * nn + z * hprev;
            }
            __syncthreads();
        }
        if (n < Hn) s_gctx[n] = s_hidden[n];
        __syncthreads();
    }

    // cluster_adj = ones - eye
    if (n < Sn * Sn) {
        int i = n / Sn, j = n % Sn;
        out_ca[b * Sn * Sn + n] = (i == j) ? 0.0f : 1.0f;
    }
}

extern "C" void kernel_launch(void* const* d_in, const int* in_sizes, int n_in,
                              void* d_out, int out_size) {
    (void)in_sizes; (void)out_size;
    // inputs: x, adj, mask, W1, b1, W2, b2, Wih, Whh, bih, bhh, Wc, bc
    int k = (n_in >= 13) ? 3 : 2;   // tolerate mask being dropped
    const float* x   = (const float*)d_in[0];
    const float* adj = (const float*)d_in[1];
    const float* W1  = (const float*)d_in[k + 0];
    const float* b1  = (const float*)d_in[k + 1];
    const float* W2  = (const float*)d_in[k + 2];
    const float* b2  = (const float*)d_in[k + 3];
    const float* Wih = (const float*)d_in[k + 4];
    const float* Whh = (const float*)d_in[k + 5];
    const float* bih = (const float*)d_in[k + 6];
    const float* bhh = (const float*)d_in[k + 7];
    const float* Wc  = (const float*)d_in[k + 8];
    const float* bc  = (const float*)d_in[k + 9];

    k_xw1<<<dim3(16, Bn), 256>>>(x, W1, b1);
    k_transpose<<<(384 * 256 + 255) / 256, 256>>>(Wih, Whh);
    k_main<<<Bn, 1024>>>(x, adj, W1, W2, b2, bih, bhh, Wc, bc, (float*)d_out);
}

// round 4
// speedup vs baseline: 2.2864x; 1.9605x over previous
#include <cuda_runtime.h>
#include <math.h>
#include <stdint.h>

// Problem constants
#define Bn 16
#define Nn 1024
#define Dn 256
#define Hn 128
#define Sn 12     // MAX_CLUSTERS
#define CSn 16    // CSIZE
#define NEGV (-1e9f)

#define PARTITIONABLE 1

// ---------------- scratch ----------------
__device__ float g_XW1t[Bn * Hn * Nn];      // [b][h][n] = x@W1[:256] + b1
__device__ float g_WihT[Dn * 3 * Hn];       // [256][384]
__device__ float g_WhhT[Hn * 3 * Hn];       // [128][384]

// ---------------- Threefry2x32 (JAX-exact) ----------------
__device__ __forceinline__ uint2 tf2x32(unsigned k0, unsigned k1, unsigned x0, unsigned x1) {
    unsigned ks2 = k0 ^ k1 ^ 0x1BD11BDAu;
    x0 += k0; x1 += k1;
#define TFR(r) { x0 += x1; x1 = (x1 << (r)) | (x1 >> (32 - (r))); x1 ^= x0; }
    TFR(13) TFR(15) TFR(26) TFR(6)   x0 += k1;  x1 += ks2 + 1u;
    TFR(17) TFR(29) TFR(16) TFR(24)  x0 += ks2; x1 += k0 + 2u;
    TFR(13) TFR(15) TFR(26) TFR(6)   x0 += k0;  x1 += k1 + 3u;
    TFR(17) TFR(29) TFR(16) TFR(24)  x0 += k1;  x1 += ks2 + 4u;
    TFR(13) TFR(15) TFR(26) TFR(6)   x0 += ks2; x1 += k0 + 5u;
#undef TFR
    return make_uint2(x0, x1);
}

struct P2 { unsigned x, y; };
constexpr unsigned rotl_c(unsigned x, int r) { return (x << r) | (x >> (32 - r)); }
constexpr P2 tf_c(unsigned k0, unsigned k1, unsigned x0, unsigned x1) {
    unsigned ks2 = k0 ^ k1 ^ 0x1BD11BDAu;
    x0 += k0; x1 += k1;
    const int R0[4] = {13, 15, 26, 6};
    const int R1[4] = {17, 29, 16, 24};
    for (int i = 0; i < 5; i++) {
        for (int j = 0; j < 4; j++) {
            int r = (i % 2 == 0) ? R0[j] : R1[j];
            x0 += x1; x1 = rotl_c(x1, r); x1 ^= x0;
        }
        int a = (i + 1) % 3, bsel = (i + 2) % 3;
        unsigned inj0 = (a == 0) ? k0 : ((a == 1) ? k1 : ks2);
        unsigned inj1 = (bsel == 0) ? k0 : ((bsel == 1) ? k1 : ks2);
        x0 += inj0; x1 += inj1 + (unsigned)(i + 1);
    }
    return P2{x0, x1};
}

struct KeyTab { unsigned a[Sn * CSn]; unsigned b[Sn * CSn]; };
constexpr KeyTab mk_keys() {
    KeyTab t{};
    unsigned k0 = 0u, k1 = 42u;
    for (int i = 0; i < Sn * CSn; i++) {
#if PARTITIONABLE
        P2 nk = tf_c(k0, k1, 0u, 0u);
        P2 sk = tf_c(k0, k1, 0u, 1u);
        t.a[i] = sk.x; t.b[i] = sk.y;
        k0 = nk.x; k1 = nk.y;
#else
        P2 l0 = tf_c(k0, k1, 0u, 2u);
        P2 l1 = tf_c(k0, k1, 1u, 3u);
        t.a[i] = l0.y; t.b[i] = l1.y;
        k0 = l0.x; k1 = l1.x;
#endif
    }
    return t;
}
static constexpr KeyTab H_KEYS = mk_keys();
__constant__ KeyTab SELKEYS = H_KEYS;

__device__ __forceinline__ unsigned rand_bits(unsigned k0, unsigned k1, unsigned g) {
#if PARTITIONABLE
    uint2 o = tf2x32(k0, k1, 0u, g);
    return o.x ^ o.y;
#else
    const unsigned m = (Bn * Nn) / 2;
    if (g < m) { uint2 o = tf2x32(k0, k1, g, g + m); return o.x; }
    else       { uint2 o = tf2x32(k0, k1, g - m, g); return o.y; }
#endif
}

// Gumbel value for node `node` at step key (k0,k1) — identical op order as before.
__device__ __forceinline__ float gumbel_val(unsigned k0, unsigned k1, int b, int node,
                                            float logit) {
    unsigned bits = rand_bits(k0, k1, (unsigned)((b << 10) + node));
    float u = __uint_as_float((bits >> 9) | 0x3f800000u) - 1.0f;
    float s1 = u + 1e-8f;
    float l1 = logf(s1);
    float s2 = (-l1) + 1e-8f;
    float l2 = logf(s2);
    return logit + (-l2);
}

__device__ __forceinline__ unsigned long long packkey(float val, int node) {
    unsigned ub = __float_as_uint(val);
    unsigned ord = (ub & 0x80000000u) ? ~ub : (ub | 0x80000000u);
    return (((unsigned long long)ord) << 32) | (unsigned)(0xFFFFFFFFu - node);
}

__device__ __forceinline__ float sigm(float v) {
    return 0.5f * tanhf(0.5f * v) + 0.5f;
}

// ---------------- Kernel 1: tiled SGEMM (unchanged from passing R3) ----------------
__global__ void __launch_bounds__(256) k_xw1(const float* __restrict__ x,
                                             const float* __restrict__ W1,
                                             const float* __restrict__ b1) {
    __shared__ float xs[64][33];
    __shared__ float ws[32][128];
    int tile = blockIdx.x;
    int b = blockIdx.y;
    int t = threadIdx.x;
    int n0 = tile * 64;
    int nl = t & 63;
    int jbase = (t >> 6) * 32;

    float acc[32];
#pragma unroll
    for (int i = 0; i < 32; i++) acc[i] = 0.f;

    for (int k0 = 0; k0 < Dn; k0 += 32) {
        for (int i = t; i < 64 * 32; i += 256) {
            int nn = i >> 5, kk = i & 31;
            xs[nn][kk] = x[((b << 10) + n0 + nn) * Dn + k0 + kk];
        }
        for (int i = t; i < 32 * 128; i += 256) {
            int kk = i >> 7, jj = i & 127;
            ws[kk][jj] = W1[(k0 + kk) * Hn + jj];
        }
        __syncthreads();
#pragma unroll 4
        for (int k = 0; k < 32; k++) {
            float xv = xs[nl][k];
            const float4* w4 = reinterpret_cast<const float4*>(&ws[k][jbase]);
#pragma unroll
            for (int i = 0; i < 8; i++) {
                float4 w = w4[i];
                acc[4 * i + 0] = fmaf(xv, w.x, acc[4 * i + 0]);
                acc[4 * i + 1] = fmaf(xv, w.y, acc[4 * i + 1]);
                acc[4 * i + 2] = fmaf(xv, w.z, acc[4 * i + 2]);
                acc[4 * i + 3] = fmaf(xv, w.w, acc[4 * i + 3]);
            }
        }
        __syncthreads();
    }
#pragma unroll
    for (int i = 0; i < 32; i++) {
        int j = jbase + i;
        g_XW1t[((b << 7) + j) * Nn + n0 + nl] = acc[i] + b1[j];
    }
}

// ---------------- Kernel 2: transpose GRU weights ----------------
__global__ void k_transpose(const float* __restrict__ Wih, const float* __restrict__ Whh) {
    int idx = blockIdx.x * blockDim.x + threadIdx.x;
    if (idx < 384 * 256) { int j = idx / 256, k = idx % 256; g_WihT[k * 384 + j] = Wih[idx]; }
    if (idx < 384 * 128) { int j = idx / 128, k = idx % 128; g_WhhT[k * 384 + j] = Whh[idx]; }
}

#define BAR384() asm volatile("bar.sync 1, 384;" ::: "memory")

// ---------------- Main kernel (v2: warp-0 grow steps, named-barrier GRU) ----------------
__global__ void __launch_bounds__(1024) k_main(
    const float* __restrict__ x, const float* __restrict__ adj,
    const float* __restrict__ W1, const float* __restrict__ W2, const float* __restrict__ b2,
    const float* __restrict__ bih, const float* __restrict__ bhh,
    const float* __restrict__ Wc, const float* __restrict__ bc,
    float* __restrict__ out) {
    int b = blockIdx.x;
    int n = threadIdx.x;
    int lane = n & 31, wid = n >> 5;

    __shared__ float s_logit[Nn];
    __shared__ float s_ctx[Hn], s_gctx[Hn], s_hidden[Hn];
    __shared__ float s_gh[3 * Hn];
    __shared__ float s_gi[Sn][3 * Hn];
    __shared__ float s_emb[Dn];
    __shared__ float s_w2[Hn];
    __shared__ float s_xmean[Dn];
    __shared__ unsigned char s_avail[Nn], s_mem[Nn], s_kmask[Nn];
    __shared__ int s_clist[Nn];
    __shared__ int s_flist[Nn];
    __shared__ int s_fcnt;
    __shared__ unsigned long long s_red[32];
    __shared__ int s_sel, s_valid;
    __shared__ int s_mlist[CSn + 1];
    __shared__ int s_mcnt;

    s_avail[n] = 1;
    if (n < Dn) {
        float s = 0.f;
        for (int m = 0; m < Nn; m++) s += x[((b << 10) + m) * Dn + n];
        s_xmean[n] = s / 1024.0f;
    }
    if (n < Hn) s_w2[n] = W2[n];
    __syncthreads();
    if (n < Hn) {
        float a = bc[n];
        for (int d = 0; d < Dn; d++) a = fmaf(s_xmean[d], Wc[d * Hn + n], a);
        s_gctx[n] = a;
        s_hidden[n] = 0.f;
    }
    float b2v = b2[0];
    __syncthreads();

    float* out_cf = out;                       // [16][12][256]
    float* out_ca = out + Bn * Sn * Dn;        // [16][12][12]
    float* out_as = out_ca + Bn * Sn * Sn;     // [16][1024][12]

    const float* arow = adj + ((long)b << 20);

    for (int c = 0; c < Sn; c++) {
        s_mem[n] = 0;
        // ctx contribution: gctx @ W1[256:384,:]  (no barrier needed before: gctx stable)
        __syncthreads();
        if (n < Hn) {
            float a = 0.f;
            for (int k = 0; k < Hn; k++) a = fmaf(s_gctx[k], W1[(Dn + k) * Hn + n], a);
            s_ctx[n] = a;
        }
        __syncthreads();
        // logits[n] = relu(XW1t + ctx) @ W2 + b2
        {
            float acc = 0.f;
            const float* px = g_XW1t + ((long)(b) << 7) * Nn + n;
#pragma unroll 8
            for (int j = 0; j < Hn; j++) {
                float v = px[j * Nn] + s_ctx[j];
                acc = fmaf(fmaxf(v, 0.f), s_w2[j], acc);
            }
            s_logit[n] = acc + b2v;
        }
        __syncthreads();

        // ---- seed selection (s = 0), block-wide ----
        {
            unsigned k0 = SELKEYS.a[c * CSn + 0], k1 = SELKEYS.b[c * CSn + 0];
            float val = NEGV;
            if (s_avail[n]) val = gumbel_val(k0, k1, b, n, s_logit[n]);
            unsigned long long pk = packkey(val, n);
            for (int off = 16; off; off >>= 1) {
                unsigned long long o = __shfl_down_sync(0xffffffffu, pk, off);
                if (o > pk) pk = o;
            }
            if (lane == 0) s_red[wid] = pk;
            __syncthreads();
            if (wid == 0) {
                unsigned long long v2 = s_red[lane];
                for (int off = 16; off; off >>= 1) {
                    unsigned long long o = __shfl_down_sync(0xffffffffu, v2, off);
                    if (o > v2) v2 = o;
                }
                if (lane == 0) {
                    s_sel = (int)(0xFFFFFFFFu - (unsigned)(v2 & 0xFFFFFFFFu));
                    unsigned ordv = (unsigned)(v2 >> 32);
                    unsigned fb = (ordv & 0x80000000u) ? (ordv ^ 0x80000000u) : ~ordv;
                    s_valid = (__uint_as_float(fb) > -1e8f) ? 1 : 0;
                }
            }
            __syncthreads();
        }
        int sel = s_sel;
        if (s_valid && n == sel) { s_avail[n] = 0; s_mem[n] = 1; }
        if (n == 0) {
            s_mcnt = s_valid ? 1 : 0;
            if (s_valid) s_mlist[0] = sel;
            s_fcnt = 0;
        }

        // ---- 2-hop BFS from seed (3 barriers) ----
        bool nb1 = (arow[(sel << 10) + n] != 0.0f);
        bool reach1 = (n == sel) || nb1;
        bool cur1 = nb1 && (n != sel);
        __syncthreads();
        if (cur1) { int p = atomicAdd(&s_fcnt, 1); s_flist[p] = n; }
        __syncthreads();
        {
            int fc = s_fcnt;
            bool nb2 = false;
            for (int f = 0; f < fc; f++)
                nb2 = nb2 || (arow[(s_flist[f] << 10) + n] != 0.0f);
            s_kmask[n] = (reach1 || nb2) ? 1 : 0;
        }
        __syncthreads();

        // ---- grow steps s = 1..15: warp 0 only, zero block barriers ----
        if (wid == 0) {
            // compact candidate list (avail & kmask)
            int cnt = 0;
            for (int base = 0; base < Nn; base += 32) {
                int node = base + lane;
                bool cd = s_avail[node] && s_kmask[node];
                unsigned mk = __ballot_sync(0xffffffffu, cd);
                if (cd) s_clist[cnt + __popc(mk & ((1u << lane) - 1u))] = node;
                cnt += __popc(mk);
            }
            int aliveCnt = cnt;
            int mc = s_mcnt;
            for (int s = 1; s < CSn; s++) {
                if (aliveCnt > 0) {
                    unsigned k0 = SELKEYS.a[c * CSn + s], k1 = SELKEYS.b[c * CSn + s];
                    unsigned long long pk =
                        (((unsigned long long)(~__float_as_uint(NEGV))) << 32);
                    for (int i = lane; i < cnt; i += 32) {
                        int node = s_clist[i];
                        if (node >= 0) {
                            float val = gumbel_val(k0, k1, b, node, s_logit[node]);
                            unsigned long long p2 = packkey(val, node);
                            if (p2 > pk) pk = p2;
                        }
                    }
                    for (int off = 16; off; off >>= 1) {
                        unsigned long long o = __shfl_xor_sync(0xffffffffu, pk, off);
                        if (o > pk) pk = o;
                    }
                    int node = (int)(0xFFFFFFFFu - (unsigned)(pk & 0xFFFFFFFFu));
                    for (int i = lane; i < cnt; i += 32)
                        if (s_clist[i] == node) s_clist[i] = -1;
                    if (lane == 0) {
                        s_avail[node] = 0; s_mem[node] = 1; s_mlist[mc] = node;
                    }
                    mc++;
                    aliveCnt--;
                }
            }
            if (lane == 0) {
                s_mcnt = mc;
                // insertion sort ascending (restores jnp ascending-index sum order)
                for (int i = 1; i < mc; i++) {
                    int v = s_mlist[i], j = i - 1;
                    while (j >= 0 && s_mlist[j] > v) { s_mlist[j + 1] = s_mlist[j]; j--; }
                    s_mlist[j + 1] = v;
                }
            }
        }
        __syncthreads();

        // ---- cluster embedding ----
        int mc = s_mcnt;
        if (n < Dn) {
            float e = 0.f;
            for (int i = 0; i < mc; i++) e += x[((b << 10) + s_mlist[i]) * Dn + n];
            e = e / fmaxf((float)mc, 1.0f);
            s_emb[n] = e;
            out_cf[((b * Sn) + c) * Dn + n] = e;
        }
        out_as[((b << 10) + n) * Sn + c] = s_mem[n] ? 1.0f : 0.0f;
        __syncthreads();

        // ---- GRU: threads 0..383 with named barriers; others skip to cluster end ----
        if (n < 3 * Hn) {
            {
                float a = bih[n];
                for (int k = 0; k < Dn; k++) a = fmaf(s_emb[k], g_WihT[k * 384 + n], a);
                s_gi[c][n] = a;
            }
            BAR384();
            for (int t2 = 0; t2 <= c; t2++) {
                {
                    float a = bhh[n];
                    for (int k = 0; k < Hn; k++) a = fmaf(s_hidden[k], g_WhhT[k * 384 + n], a);
                    s_gh[n] = a;
                }
                BAR384();
                if (n < Hn) {
                    float ir = s_gi[t2][n], iz = s_gi[t2][Hn + n], inn = s_gi[t2][2 * Hn + n];
                    float hr = s_gh[n], hz = s_gh[Hn + n], hn = s_gh[2 * Hn + n];
                    float r = sigm(ir + hr);
                    float z = sigm(iz + hz);
                    float nn = tanhf(inn + r * hn);
                    float hprev = s_hidden[n];
                    s_hidden[n] = (1.0f - z) * nn + z * hprev;
                }
                BAR384();
            }
            if (n < Hn) s_gctx[n] = s_hidden[n];
        }
        __syncthreads();
    }

    // cluster_adj = ones - eye
    if (n < Sn * Sn) {
        int i = n / Sn, j = n % Sn;
        out_ca[b * Sn * Sn + n] = (i == j) ? 0.0f : 1.0f;
    }
}

extern "C" void kernel_launch(void* const* d_in, const int* in_sizes, int n_in,
                              void* d_out, int out_size) {
    (void)in_sizes; (void)out_size;
    int k = (n_in >= 13) ? 3 : 2;
    const float* x   = (const float*)d_in[0];
    const float* adj = (const float*)d_in[1];
    const float* W1  = (const float*)d_in[k + 0];
    const float* b1  = (const float*)d_in[k + 1];
    const float* W2  = (const float*)d_in[k + 2];
    const float* b2  = (const float*)d_in[k + 3];
    const float* Wih = (const float*)d_in[k + 4];
    const float* Whh = (const float*)d_in[k + 5];
    const float* bih = (const float*)d_in[k + 6];
    const float* bhh = (const float*)d_in[k + 7];
    const float* Wc  = (const float*)d_in[k + 8];
    const float* bc  = (const float*)d_in[k + 9];

    k_xw1<<<dim3(16, Bn), 256>>>(x, W1, b1);
    k_transpose<<<(384 * 256 + 255) / 256, 256>>>(Wih, Whh);
    k_main<<<Bn, 1024>>>(x, adj, W1, W2, b2, bih, bhh, Wc, bc, (float*)d_out);
}